// round 1
// baseline (speedup 1.0000x reference)
#include <cuda_runtime.h>
#include <math_constants.h>

// Problem constants
#define C_IN  64
#define F_OUT 128
#define NPOS  9
#define KTOT  (NPOS * C_IN)      // 576
#define HH    128
#define WW    128
#define NB    16

// Scratch for the effective ternary weights AW (3,3,64,128) flat = (576,128)
__device__ float g_AW[KTOT * F_OUT];

// ---------------------------------------------------------------------------
// Kernel 1: compute AW = top4_mask(D + gumbel) * sign(kern)
// One thread per (f, c) pair: 128*64 = 8192 threads.
// logits reshape (3,3,64,128)->(128,64,9) is a flat reinterpret, so the 9
// values for pair t live at flat offsets [t*9, t*9+9) of D / gumbel_u, and the
// mask applies at the SAME flat offsets of kern -> AW.
// ---------------------------------------------------------------------------
__global__ void weights_kernel(const float* __restrict__ D,
                               const float* __restrict__ u,
                               const float* __restrict__ kern) {
    int t = blockIdx.x * blockDim.x + threadIdx.x;
    if (t >= F_OUT * C_IN) return;

    const float* Dp = D + t * NPOS;
    const float* up = u + t * NPOS;

    float pert[NPOS];
#pragma unroll
    for (int n = 0; n < NPOS; ++n) {
        float g = -0.001f * logf(-logf(up[n] + 1e-20f) + 1e-20f);
        pert[n] = Dp[n] + g;
    }

    // top-4 by value (values are continuous; ties have measure zero)
    unsigned sel = 0;
#pragma unroll
    for (int j = 0; j < 4; ++j) {
        int   bi = 0;
        float bv = -CUDART_INF_F;
#pragma unroll
        for (int n = 0; n < NPOS; ++n) {
            bool taken = (sel >> n) & 1u;
            if (!taken && pert[n] > bv) { bv = pert[n]; bi = n; }
        }
        sel |= (1u << bi);
    }

    const float* kp = kern + t * NPOS;
    float*       op = g_AW + t * NPOS;
#pragma unroll
    for (int n = 0; n < NPOS; ++n) {
        float w = kp[n];
        float s = (w > 0.f) ? 1.f : ((w < 0.f) ? -1.f : 0.f);
        op[n] = ((sel >> n) & 1u) ? s : 0.f;
    }
}

// ---------------------------------------------------------------------------
// Kernel 2: implicit-GEMM 3x3 SAME conv, NHWC.
// C[M=262144, 128] = Xpatch[M, 576] * g_AW[576, 128], +bias, ReLU.
// Tile: BM=64 pixels (contiguous along w), BN=128 (all f), BK=64 (= C_IN of
// one kernel position). 256 threads, each computes a 4(m) x 8(n) register tile.
// ---------------------------------------------------------------------------
__global__ __launch_bounds__(256)
void conv_kernel(const float* __restrict__ x,
                 const float* __restrict__ bias,
                 float* __restrict__ out) {
    __shared__ float  As[64][64];   // [ci][tw]  (transposed A tile)
    __shared__ float4 Ws[64][32];   // [k][f/4]  (64 x 128 weight tile)

    const int tid  = threadIdx.x;
    const int pix0 = blockIdx.x << 6;             // 64 pixels per CTA
    const int n    = pix0 >> 14;                  // / (128*128)
    const int h    = (pix0 >> 7) & 127;
    const int w0   = pix0 & 127;                  // 0 or 64

    const int tm0 = (tid & 15) << 2;              // 0..60, step 4
    const int tn4 = (tid >> 4) << 1;              // float4 col index, tn0 = tn4*4

    float acc[4][8];
#pragma unroll
    for (int i = 0; i < 4; ++i)
#pragma unroll
        for (int j = 0; j < 8; ++j) acc[i][j] = 0.f;

    const int ltw  = tid & 63;                    // loader pixel-in-tile
    const int lci0 = tid >> 6;                    // loader ci4 base (0..3)

#pragma unroll 1
    for (int kpos = 0; kpos < NPOS; ++kpos) {
        const int  dh = kpos / 3 - 1;
        const int  dw = kpos % 3 - 1;
        const int  hh = h + dh;
        const int  ww = w0 + ltw + dw;
        const bool ok = ((unsigned)hh < 128u) && ((unsigned)ww < 128u);
        const float* src = x + (((long)n * HH + hh) * WW + ww) * C_IN;

        // A tile: 64 pixels x 64 channels; store transposed [ci][tw]
#pragma unroll
        for (int i = 0; i < 4; ++i) {
            int ci = (lci0 + 4 * i) << 2;         // 0..60 step 4
            float4 v = make_float4(0.f, 0.f, 0.f, 0.f);
            if (ok) v = *reinterpret_cast<const float4*>(src + ci);
            As[ci + 0][ltw] = v.x;
            As[ci + 1][ltw] = v.y;
            As[ci + 2][ltw] = v.z;
            As[ci + 3][ltw] = v.w;
        }

        // W tile: rows [kpos*64, kpos*64+64) of g_AW, fully coalesced
        const float4* Wg = reinterpret_cast<const float4*>(g_AW + kpos * (C_IN * F_OUT));
#pragma unroll
        for (int i = 0; i < 8; ++i) {
            int s = tid + (i << 8);               // 0..2047
            Ws[s >> 5][s & 31] = Wg[s];
        }
        __syncthreads();

#pragma unroll 16
        for (int k = 0; k < 64; ++k) {
            float4 a  = *reinterpret_cast<const float4*>(&As[k][tm0]);
            float4 b0 = Ws[k][tn4];
            float4 b1 = Ws[k][tn4 + 1];
            float av[4] = {a.x, a.y, a.z, a.w};
            float bv[8] = {b0.x, b0.y, b0.z, b0.w, b1.x, b1.y, b1.z, b1.w};
#pragma unroll
            for (int i = 0; i < 4; ++i)
#pragma unroll
                for (int j = 0; j < 8; ++j)
                    acc[i][j] = fmaf(av[i], bv[j], acc[i][j]);
        }
        __syncthreads();
    }

    // Epilogue: + bias, ReLU, write out[pixel][f]
    const int tn0 = tn4 << 2;
    float bb[8];
#pragma unroll
    for (int j = 0; j < 8; ++j) bb[j] = bias[tn0 + j];

#pragma unroll
    for (int i = 0; i < 4; ++i) {
        float4 o0, o1;
        o0.x = fmaxf(acc[i][0] + bb[0], 0.f);
        o0.y = fmaxf(acc[i][1] + bb[1], 0.f);
        o0.z = fmaxf(acc[i][2] + bb[2], 0.f);
        o0.w = fmaxf(acc[i][3] + bb[3], 0.f);
        o1.x = fmaxf(acc[i][4] + bb[4], 0.f);
        o1.y = fmaxf(acc[i][5] + bb[5], 0.f);
        o1.z = fmaxf(acc[i][6] + bb[6], 0.f);
        o1.w = fmaxf(acc[i][7] + bb[7], 0.f);
        float* dst = out + (long)(pix0 + tm0 + i) * F_OUT + tn0;
        *reinterpret_cast<float4*>(dst)     = o0;
        *reinterpret_cast<float4*>(dst + 4) = o1;
    }
}

// ---------------------------------------------------------------------------
// Launch: inputs per metadata order: x, kern, b, D, gumbel_u
// ---------------------------------------------------------------------------
extern "C" void kernel_launch(void* const* d_in, const int* in_sizes, int n_in,
                              void* d_out, int out_size) {
    const float* x    = (const float*)d_in[0];
    const float* kern = (const float*)d_in[1];
    const float* b    = (const float*)d_in[2];
    const float* D    = (const float*)d_in[3];
    const float* u    = (const float*)d_in[4];
    float* out = (float*)d_out;

    weights_kernel<<<(F_OUT * C_IN + 255) / 256, 256>>>(D, u, kern);

    const int m_tiles = (NB * HH * WW) / 64;      // 4096
    conv_kernel<<<m_tiles, 256>>>(x, b, out);
}